// round 3
// baseline (speedup 1.0000x reference)
#include <cuda_runtime.h>
#include <math.h>

#define NN 8192
#define EMAX 262144

// Scratch (allocation-free rule: device globals)
__device__ int   g_cnt   [NN];
__device__ int   g_fill  [NN];
__device__ int   g_rowptr[NN + 1];
__device__ int   g_col   [EMAX];
__device__ float g_dinv  [NN];
__device__ float g_h2    [NN * 8];
__device__ float g_x2    [NN * 8];

// Copy a slice [lo,hi) of float4s with the block's share of copy threads.
__device__ __forceinline__ void do_copy(const float4* __restrict__ src,
                                        float4* __restrict__ dst,
                                        long lo, long hi, int sb) {
    long t = (long)(blockIdx.x - sb) * blockDim.x + threadIdx.x;
    long T = (long)(gridDim.x - sb) * blockDim.x;
    for (long i = lo + t; i < hi; i += T) dst[i] = src[i];
}

// ---------------------------------------------------------------------------
// Stage 1: zero counters (+ copy slice)
__global__ void k_zero_c(const float4* src, float4* dst, long lo, long hi, int sb) {
    if ((int)blockIdx.x >= sb) { do_copy(src, dst, lo, hi, sb); return; }
    int t0 = blockIdx.x * blockDim.x + threadIdx.x;
    int T  = sb * blockDim.x;
    for (int i = t0; i < NN; i += T) { g_cnt[i] = 0; g_fill[i] = 0; }
}

// Stage 2: in-degree histogram (+ copy slice)
__global__ void k_count_c(const int* __restrict__ ei, int E,
                          const float4* src, float4* dst, long lo, long hi, int sb) {
    if ((int)blockIdx.x >= sb) { do_copy(src, dst, lo, hi, sb); return; }
    int t0 = blockIdx.x * blockDim.x + threadIdx.x;
    int T  = sb * blockDim.x;
    for (int e = t0; e < E; e += T) atomicAdd(&g_cnt[ei[E + e]], 1);
}

// Stage 3: single-block scan -> rowptr, dinv (+ copy slice). sb == 1.
__global__ void k_scan_c(const float4* src, float4* dst, long lo, long hi, int sb) {
    if ((int)blockIdx.x >= sb) { do_copy(src, dst, lo, hi, sb); return; }
    __shared__ int sp[256];
    int t = threadIdx.x;                 // 256 threads, 32 elems each
    int base = t * 32;
    int s = 0;
#pragma unroll
    for (int k = 0; k < 32; k++) {
        int cv = g_cnt[base + k];
        g_rowptr[base + k] = s;          // local prefix, offset added below
        g_dinv[base + k] = rsqrtf((float)cv + 1.0f);
        s += cv;
    }
    sp[t] = s;
    __syncthreads();
    for (int o = 1; o < 256; o <<= 1) {  // inclusive Hillis-Steele
        int v = (t >= o) ? sp[t - o] : 0;
        __syncthreads();
        sp[t] += v;
        __syncthreads();
    }
    int off = sp[t] - s;                 // exclusive offset
#pragma unroll
    for (int k = 0; k < 32; k++) g_rowptr[base + k] += off;
    if (t == 255) g_rowptr[NN] = sp[255];
}

// Stage 4: CSR fill (+ copy slice)
__global__ void k_fill_c(const int* __restrict__ ei, int E,
                         const float4* src, float4* dst, long lo, long hi, int sb) {
    if ((int)blockIdx.x >= sb) { do_copy(src, dst, lo, hi, sb); return; }
    int t0 = blockIdx.x * blockDim.x + threadIdx.x;
    int T  = sb * blockDim.x;
    for (int e = t0; e < E; e += T) {
        int s = ei[e];
        int d = ei[E + e];
        int p = g_rowptr[d] + atomicAdd(&g_fill[d], 1);
        g_col[p] = s;
    }
}

// Stage 5: conv1 gather + bias + ReLU + 16x8 matmul (+ copy slice)
__global__ void k_conv1_c(const float* __restrict__ W1,
                          const float* __restrict__ b1,
                          const float* __restrict__ W2,
                          const float4* src, float4* dst, long lo, long hi, int sb) {
    if ((int)blockIdx.x >= sb) { do_copy(src, dst, lo, hi, sb); return; }
    int t0 = blockIdx.x * blockDim.x + threadIdx.x;
    int T  = sb * blockDim.x;
    int lane  = threadIdx.x & 31;
    int gbase = lane & 16;
    for (int t = t0; t < NN * 16; t += T) {     // NN*16 and T are multiples of 32
        int n = t >> 4;
        int f = t & 15;
        float dn  = g_dinv[n];
        int   beg = g_rowptr[n], end = g_rowptr[n + 1];
        float acc = 0.0f;
        for (int e = beg; e < end; e++) {
            int s = g_col[e];
            acc += g_dinv[s] * W1[(size_t)s * 16 + f];
        }
        float xf = fmaxf(dn * acc + dn * dn * W1[(size_t)n * 16 + f] + b1[f], 0.0f);
        float h = 0.0f;
#pragma unroll
        for (int k = 0; k < 16; k++) {
            float xk = __shfl_sync(0xffffffffu, xf, gbase + k);
            h += xk * W2[k * 8 + (f & 7)];
        }
        if (f < 8) g_h2[(size_t)n * 8 + f] = h;
    }
}

// Stage 6: conv2 gather + bias + ReLU (+ copy slice)
__global__ void k_conv2_c(const float* __restrict__ b2,
                          const float4* src, float4* dst, long lo, long hi, int sb) {
    if ((int)blockIdx.x >= sb) { do_copy(src, dst, lo, hi, sb); return; }
    int t0 = blockIdx.x * blockDim.x + threadIdx.x;
    int T  = sb * blockDim.x;
    for (int t = t0; t < NN * 8; t += T) {
        int n = t >> 3;
        int j = t & 7;
        float dn  = g_dinv[n];
        int   beg = g_rowptr[n], end = g_rowptr[n + 1];
        float acc = 0.0f;
        for (int e = beg; e < end; e++) {
            int s = g_col[e];
            acc += g_dinv[s] * g_h2[(size_t)s * 8 + j];
        }
        float v = dn * acc + dn * dn * g_h2[(size_t)n * 8 + j] + b2[j];
        g_x2[(size_t)n * 8 + j] = fmaxf(v, 0.0f);
    }
}

// Stage 7 (separate kernel: must order after ALL copy writes)
__global__ void k_edgeout(const int* __restrict__ ue,
                          const float* __restrict__ Wfc,
                          const float* __restrict__ bfc,
                          float* __restrict__ out, int U) {
    int i = blockIdx.x * blockDim.x + threadIdx.x;
    if (i >= U) return;
    int u = ue[2 * i];
    int v = ue[2 * i + 1];
    float s = bfc[0];
#pragma unroll
    for (int f = 0; f < 8; f++) {
        s += g_x2[(size_t)u * 8 + f] * Wfc[f];
        s += g_x2[(size_t)v * 8 + f] * Wfc[8 + f];
    }
    float o = 1.0f / (1.0f + expf(-s));
    out[(size_t)u * NN + v] = o;
    out[(size_t)v * NN + u] = 1.0f - o;
}

extern "C" void kernel_launch(void* const* d_in, const int* in_sizes, int n_in,
                              void* d_out, int out_size) {
    const float* adj = (const float*)d_in[0];
    const float* W1  = (const float*)d_in[1];
    const float* b1  = (const float*)d_in[2];
    const float* W2  = (const float*)d_in[3];
    const float* b2  = (const float*)d_in[4];
    const float* Wfc = (const float*)d_in[5];
    const float* bfc = (const float*)d_in[6];
    const int*   ei  = (const int*)d_in[7];
    const int*   ue  = (const int*)d_in[8];

    int E = in_sizes[7] / 2;
    int U = in_sizes[8] / 2;

    const int B = 256;
    const int G = 640;                       // total blocks per fused kernel
    const float4* src = (const float4*)adj;
    float4*       dst = (float4*)d_out;
    long n4 = (long)out_size / 4;

    long cut[7];
    for (int i = 0; i <= 6; i++) cut[i] = n4 * i / 6;

    k_zero_c <<<G, B>>>(src, dst, cut[0], cut[1], 16);
    k_count_c<<<G, B>>>(ei, E, src, dst, cut[1], cut[2], 48);
    k_scan_c <<<G, B>>>(src, dst, cut[2], cut[3], 1);
    k_fill_c <<<G, B>>>(ei, E, src, dst, cut[3], cut[4], 48);
    k_conv1_c<<<G, B>>>(W1, b1, W2, src, dst, cut[4], cut[5], 96);
    k_conv2_c<<<G, B>>>(b2, src, dst, cut[5], cut[6], 48);
    k_edgeout<<<(U + B - 1) / B, B>>>(ue, Wfc, bfc, (float*)d_out, U);
}

// round 4
// speedup vs baseline: 1.1473x; 1.1473x over previous
#include <cuda_runtime.h>
#include <math.h>

#define NN 8192
#define EMAX 262144
#define CB 96            // chain blocks (bid 0..CB-1), rest are copy blocks
#define THREADS 256

// Scratch (allocation-free rule: device globals)
__device__ int   g_cnt   [NN];
__device__ int   g_fill  [NN];
__device__ int   g_rowptr[NN + 1];
__device__ int   g_col   [EMAX];
__device__ float g_dinv  [NN];
__device__ float g_h2    [NN * 8];
__device__ float g_x2    [NN * 8];
__device__ int   g_bar;        // chain stage barrier (reset at kernel end)
__device__ int   g_copydone;   // copy blocks completed
__device__ int   g_exit;       // chain blocks done (for reset protocol)

// Barrier among the CB chain blocks only. gpu-scope fences on both sides:
// release writes before arriving, invalidate L1 before reading peers' data.
__device__ __forceinline__ void chain_barrier(int target) {
    __threadfence();
    __syncthreads();
    if (threadIdx.x == 0) {
        atomicAdd(&g_bar, 1);
        while (atomicAdd(&g_bar, 0) < target) { }
    }
    __syncthreads();
    __threadfence();
}

__global__ void __launch_bounds__(THREADS)
k_fused(const float4* __restrict__ src, float4* __restrict__ dst, long n4,
        const int* __restrict__ ei, int E,
        const float* __restrict__ W1, const float* __restrict__ b1,
        const float* __restrict__ W2, const float* __restrict__ b2,
        const float* __restrict__ Wfc, const float* __restrict__ bfc,
        const int* __restrict__ ue, int U, int CG)
{
    int bid = blockIdx.x;

    // ---------------- copy role: stream 256MB, never waits ----------------
    if (bid >= CB) {
        long T = (long)CG * THREADS;
        long i = (long)(bid - CB) * THREADS + threadIdx.x;
        for (; i + 3 * T < n4; i += 4 * T) {
            float4 a0 = src[i];
            float4 a1 = src[i + T];
            float4 a2 = src[i + 2 * T];
            float4 a3 = src[i + 3 * T];
            dst[i]         = a0;
            dst[i + T]     = a1;
            dst[i + 2 * T] = a2;
            dst[i + 3 * T] = a3;
        }
        for (; i < n4; i += T) dst[i] = src[i];
        __threadfence();               // release copy writes
        __syncthreads();
        if (threadIdx.x == 0) atomicAdd(&g_copydone, 1);
        return;
    }

    // ---------------- chain role: CSR build + 2 GCN layers ----------------
    int t0 = bid * THREADS + threadIdx.x;
    const int T = CB * THREADS;        // 24576 chain threads
    int lane  = threadIdx.x & 31;
    int gbase = lane & 16;

    // stage 1: zero counters
    for (int i = t0; i < NN; i += T) { g_cnt[i] = 0; g_fill[i] = 0; }
    chain_barrier(CB * 1);

    // stage 2: in-degree histogram
    for (int e = t0; e < E; e += T) atomicAdd(&g_cnt[ei[E + e]], 1);
    chain_barrier(CB * 2);

    // stage 3: scan -> rowptr, dinv (block 0 only)
    if (bid == 0) {
        __shared__ int sp[THREADS];
        int t = threadIdx.x;           // 256 threads, 32 elems each
        int base = t * 32;
        int s = 0;
#pragma unroll
        for (int k = 0; k < 32; k++) {
            int cv = g_cnt[base + k];
            g_rowptr[base + k] = s;    // local prefix; block offset added below
            g_dinv[base + k] = rsqrtf((float)cv + 1.0f);
            s += cv;
        }
        sp[t] = s;
        __syncthreads();
        for (int o = 1; o < THREADS; o <<= 1) {
            int v = (t >= o) ? sp[t - o] : 0;
            __syncthreads();
            sp[t] += v;
            __syncthreads();
        }
        int off = sp[t] - s;
#pragma unroll
        for (int k = 0; k < 32; k++) g_rowptr[base + k] += off;
        if (t == THREADS - 1) g_rowptr[NN] = sp[THREADS - 1];
    }
    chain_barrier(CB * 3);

    // stage 4: CSR fill (bucket src by dst)
    for (int e = t0; e < E; e += T) {
        int s = ei[e];
        int d = ei[E + e];
        int p = g_rowptr[d] + atomicAdd(&g_fill[d], 1);
        g_col[p] = s;
    }
    chain_barrier(CB * 4);

    // stage 5: conv1 gather + bias + ReLU + 16x8 matmul (16 lanes/node)
    for (int t = t0; t < NN * 16; t += T) {   // warp-uniform trip counts
        int n = t >> 4;
        int f = t & 15;
        float dn  = g_dinv[n];
        int   beg = g_rowptr[n], end = g_rowptr[n + 1];
        float acc = 0.0f;
        for (int e = beg; e < end; e++) {
            int s = g_col[e];
            acc += g_dinv[s] * W1[(size_t)s * 16 + f];
        }
        float xf = fmaxf(dn * acc + dn * dn * W1[(size_t)n * 16 + f] + b1[f], 0.0f);
        float h = 0.0f;
#pragma unroll
        for (int k = 0; k < 16; k++) {
            float xk = __shfl_sync(0xffffffffu, xf, gbase + k);
            h += xk * W2[k * 8 + (f & 7)];
        }
        if (f < 8) g_h2[(size_t)n * 8 + f] = h;
    }
    chain_barrier(CB * 5);

    // stage 6: conv2 gather + bias + ReLU (8 lanes/node)
    for (int t = t0; t < NN * 8; t += T) {
        int n = t >> 3;
        int j = t & 7;
        float dn  = g_dinv[n];
        int   beg = g_rowptr[n], end = g_rowptr[n + 1];
        float acc = 0.0f;
        for (int e = beg; e < end; e++) {
            int s = g_col[e];
            acc += g_dinv[s] * g_h2[(size_t)s * 8 + j];
        }
        float v = dn * acc + dn * dn * g_h2[(size_t)n * 8 + j] + b2[j];
        g_x2[(size_t)n * 8 + j] = fmaxf(v, 0.0f);
    }
    chain_barrier(CB * 6);

    // wait for ALL copy writes to land (WAW ordering with edgeout)
    if (threadIdx.x == 0) {
        while (atomicAdd(&g_copydone, 0) < CG) { }
    }
    __syncthreads();
    __threadfence();

    // stage 7: orientation head overwrites
    float wf[16];
#pragma unroll
    for (int f = 0; f < 16; f++) wf[f] = Wfc[f];
    float bias = bfc[0];
    for (int i = t0; i < U; i += T) {
        int u = ue[2 * i];
        int v = ue[2 * i + 1];
        float s = bias;
#pragma unroll
        for (int f = 0; f < 8; f++) {
            s += g_x2[(size_t)u * 8 + f] * wf[f];
            s += g_x2[(size_t)v * 8 + f] * wf[8 + f];
        }
        float o = 1.0f / (1.0f + expf(-s));
        dst[0];  // no-op keepalive (avoids unused warnings in some paths)
        ((float*)dst)[(size_t)u * NN + v] = o;
        ((float*)dst)[(size_t)v * NN + u] = 1.0f - o;
    }

    // exit protocol: block 0 resets counters after all chain blocks are done
    __threadfence();
    __syncthreads();
    if (threadIdx.x == 0) {
        atomicAdd(&g_exit, 1);
        if (bid == 0) {
            while (atomicAdd(&g_exit, 0) < CB) { }
            g_bar = 0;
            g_copydone = 0;
            g_exit = 0;
            __threadfence();
        }
    }
}

extern "C" void kernel_launch(void* const* d_in, const int* in_sizes, int n_in,
                              void* d_out, int out_size) {
    const float* adj = (const float*)d_in[0];
    const float* W1  = (const float*)d_in[1];
    const float* b1  = (const float*)d_in[2];
    const float* W2  = (const float*)d_in[3];
    const float* b2  = (const float*)d_in[4];
    const float* Wfc = (const float*)d_in[5];
    const float* bfc = (const float*)d_in[6];
    const int*   ei  = (const int*)d_in[7];
    const int*   ue  = (const int*)d_in[8];

    int E = in_sizes[7] / 2;
    int U = in_sizes[8] / 2;

    const int G  = 888;            // 148 SMs x 6 blocks: single co-resident wave
    const int CG = G - CB;         // copy blocks
    long n4 = (long)out_size / 4;  // NN*NN divisible by 4

    k_fused<<<G, THREADS>>>((const float4*)adj, (float4*)d_out, n4,
                            ei, E, W1, b1, W2, b2, Wfc, bfc, ue, U, CG);
}